// round 11
// baseline (speedup 1.0000x reference)
#include <cuda_runtime.h>
#include <cuda_bf16.h>
#include <cstdint>

#define B_    128
#define T_    1024
#define RNN_  1024
#define EMB_  512
#define ATT_  128
#define NF_   32
#define KS_   31
#define PAD_  15

// energies GEMM per 128-t tile: D[128,128] = A[t,192] * B[192,a], B dedup to 128 rows
// s0-3: Ahi x Bhi, s4-7: Alo x Bhi, s8-11: Ahi x Blo
#define LDAB_  136                              // bf16 elems per smem row (272 B)
#define OFF_B_    (128 * LDAB_ * 2)             // 34816
#define OFF_AWR_  (OFF_B_ + 128 * LDAB_ * 2)    // 69632: aw rows 2 x 1056 f
#define OFF_V_    (OFF_AWR_ + 8448)             // 78080
#define OFF_E_    (OFF_V_ + 512)                // 78592: energies 2 x 1024 f (also pq scratch)
#define OFF_RED_  (OFF_E_ + 8192)               // 86784
#define OFF_HID_  (OFF_RED_ + 256)              // 87040: hidden row 1024 f
#define OFF_P_    (OFF_HID_ + 4096)             // 91136: tile p[128]
#define ESMEM_    (OFF_P_ + 512)                // 91648

// scratch inside the (not yet built) A region during staging:
#define SCR_WLOC_  0          // 4096 f = 16384 B
#define SCR_WCONV_ 16384      // 1984 f = 7936 B (ends at 24320 < 34816)

// ---------------- helpers ----------------
__device__ __forceinline__ float tanh_fast(float x) {
    float y; asm("tanh.approx.f32 %0, %1;" : "=f"(y) : "f"(x)); return y;
}
__device__ __forceinline__ uint32_t smem_u32(const void* p) {
    uint32_t a;
    asm("{ .reg .u64 t; cvta.to.shared.u64 t, %1; cvt.u32.u64 %0, t; }" : "=r"(a) : "l"(p));
    return a;
}
__device__ __forceinline__ void ldsm_x4(uint32_t* r, uint32_t addr) {
    asm volatile("ldmatrix.sync.aligned.m8n8.x4.shared.b16 {%0,%1,%2,%3}, [%4];"
                 : "=r"(r[0]), "=r"(r[1]), "=r"(r[2]), "=r"(r[3]) : "r"(addr));
}
__device__ __forceinline__ void ldsm_x2t(uint32_t& b0, uint32_t& b1, uint32_t addr) {
    asm volatile("ldmatrix.sync.aligned.m8n8.x2.trans.shared.b16 {%0,%1}, [%2];"
                 : "=r"(b0), "=r"(b1) : "r"(addr));
}
__device__ __forceinline__ void mma_bf16(float* d, const uint32_t* a, uint32_t b0, uint32_t b1) {
    asm volatile("mma.sync.aligned.m16n8k16.row.col.f32.bf16.bf16.f32 "
                 "{%0,%1,%2,%3}, {%4,%5,%6,%7}, {%8,%9}, {%0,%1,%2,%3};"
                 : "+f"(d[0]), "+f"(d[1]), "+f"(d[2]), "+f"(d[3])
                 : "r"(a[0]), "r"(a[1]), "r"(a[2]), "r"(a[3]), "r"(b0), "r"(b1));
}

// ====== Single fused kernel: pq + W2 + MMA energies + online softmax-context ======
// grid B_, 512 threads, 1 block per b
__global__ __launch_bounds__(512, 1) void fused_kernel(
    const float* __restrict__ aw,      // [B,2,T]
    const float* __restrict__ pmem,    // [B,T,ATT]
    const float* __restrict__ vvec,    // [ATT]
    const unsigned char* __restrict__ mask,
    const float* __restrict__ hidden,  // [B,RNN]
    const float* __restrict__ wq,      // [RNN,ATT]
    const float* __restrict__ wconv,   // [NF,62]
    const float* __restrict__ wloc,    // [NF,ATT]
    const float* __restrict__ memory,  // [B,T,EMB]
    float* __restrict__ out)           // [B*EMB ctx | B*T weights]
{
    extern __shared__ __align__(16) char sm[];
    const uint32_t sbase = smem_u32(sm);

    const int b    = blockIdx.x;
    const int tid  = threadIdx.x;
    const int wm   = tid >> 5, lane = tid & 31;
    const int slab = wm >> 1;          // 0..7: t rows [16*slab, 16*slab+16)
    const int nh   = wm & 1;           // 0..1: n-tiles [8*nh, 8*nh+8)

    float* s_awr = (float*)(sm + OFF_AWR_);   // [2][1056]
    float* s_v   = (float*)(sm + OFF_V_);
    float* s_e   = (float*)(sm + OFF_E_);     // [2][1024]; pq scratch early
    float* s_red = (float*)(sm + OFF_RED_);
    float* s_hid = (float*)(sm + OFF_HID_);
    float* s_p   = (float*)(sm + OFF_P_);
    __nv_bfloat16* sB = (__nv_bfloat16*)(sm + OFF_B_);

    float* out_w = out + (size_t)B_ * EMB_;

    // ---------- staging ----------
    for (int idx = tid; idx < 2112; idx += 512) {
        int ch = idx / 1056, i = idx - ch * 1056;
        int gt = i - 16;
        s_awr[idx] = (gt >= 0 && gt < T_) ? aw[((size_t)b * 2 + ch) * T_ + gt] : 0.f;
    }
    if (tid < 128) s_v[tid] = vvec[tid];
    s_hid[tid]       = hidden[(size_t)b * RNN_ + tid];
    s_hid[tid + 512] = hidden[(size_t)b * RNN_ + tid + 512];
    {
        float* s_wloc  = (float*)(sm + SCR_WLOC_);
        float* s_wconv = (float*)(sm + SCR_WCONV_);
        #pragma unroll
        for (int i = 0; i < 8; ++i) s_wloc[tid + 512 * i] = wloc[tid + 512 * i];
        for (int m = tid; m < NF_ * 62; m += 512) s_wconv[m] = wconv[m];
    }
    __syncthreads();

    // ---------- phase A: pq partials + W2 -> B rows ----------
    {
        const int kq = tid >> 5, a4 = tid & 31;
        const float4* wq4 = (const float4*)wq + (size_t)(kq * 64) * (ATT_ / 4) + a4;
        const float*  hp  = s_hid + kq * 64;
        float4 acc0 = make_float4(0.f, 0.f, 0.f, 0.f);
        float4 acc1 = make_float4(0.f, 0.f, 0.f, 0.f);
        #pragma unroll 8
        for (int k = 0; k < 64; k += 2) {
            float h0 = hp[k], h1 = hp[k + 1];
            float4 w0 = wq4[(size_t)k * (ATT_ / 4)];
            float4 w1 = wq4[(size_t)(k + 1) * (ATT_ / 4)];
            acc0.x = fmaf(h0, w0.x, acc0.x);
            acc0.y = fmaf(h0, w0.y, acc0.y);
            acc0.z = fmaf(h0, w0.z, acc0.z);
            acc0.w = fmaf(h0, w0.w, acc0.w);
            acc1.x = fmaf(h1, w1.x, acc1.x);
            acc1.y = fmaf(h1, w1.y, acc1.y);
            acc1.z = fmaf(h1, w1.z, acc1.z);
            acc1.w = fmaf(h1, w1.w, acc1.w);
        }
        acc0.x += acc1.x; acc0.y += acc1.y; acc0.z += acc1.z; acc0.w += acc1.w;
        ((float4*)s_e)[kq * 32 + a4] = acc0;

        const float* s_wloc  = (const float*)(sm + SCR_WLOC_);
        const float* s_wconv = (const float*)(sm + SCR_WCONV_);
        for (int m = tid; m < 62 * 128; m += 512) {
            int j = m >> 7, a = m & 127;
            float acc = 0.f;
            #pragma unroll 8
            for (int f = 0; f < NF_; ++f)
                acc = fmaf(s_wconv[f * 62 + j], s_wloc[f * ATT_ + a], acc);
            __nv_bfloat16 hi = __float2bfloat16_rn(acc);
            sB[j * LDAB_ + a]        = hi;
            sB[(64 + j) * LDAB_ + a] = __float2bfloat16_rn(acc - __bfloat162float(hi));
        }
        if (tid < 128) {
            sB[ 63 * LDAB_ + tid] = __float2bfloat16_rn(0.f);
            sB[127 * LDAB_ + tid] = __float2bfloat16_rn(0.f);
        }
    }
    __syncthreads();

    // ---------- phase B: pq reduce -> B rows 62/126; const A cols ----------
    if (tid < 32) {
        float4 r = ((const float4*)s_e)[tid];
        #pragma unroll
        for (int q = 1; q < 16; ++q) {
            float4 v = ((const float4*)s_e)[q * 32 + tid];
            r.x += v.x; r.y += v.y; r.z += v.z; r.w += v.w;
        }
        float vals[4] = {r.x, r.y, r.z, r.w};
        #pragma unroll
        for (int c = 0; c < 4; ++c) {
            int col = 4 * tid + c;
            __nv_bfloat16 hi = __float2bfloat16_rn(vals[c]);
            sB[ 62 * LDAB_ + col] = hi;
            sB[126 * LDAB_ + col] = __float2bfloat16_rn(vals[c] - __bfloat162float(hi));
        }
    }
    if (tid < 128) {
        __nv_bfloat16* arow = (__nv_bfloat16*)(sm + tid * (LDAB_ * 2));
        arow[62]  = __float2bfloat16_rn(1.f);
        arow[63]  = __float2bfloat16_rn(0.f);
        arow[126] = __float2bfloat16_rn(0.f);
        arow[127] = __float2bfloat16_rn(0.f);
    }

    const uint32_t aRowAddr = sbase + (16 * slab + (lane & 15)) * (LDAB_ * 2) + (lane >> 4) * 16;
    const uint32_t bRowAddr = sbase + OFF_B_ + (lane & 15) * (LDAB_ * 2) + nh * 128;
    const int rowL = tid >> 2;
    const int jq   = tid & 3;

    const float NINF = -__int_as_float(0x7f800000);
    float run_max = NINF;
    float cacc0 = 0.f, cacc1 = 0.f, cacc2 = 0.f, cacc3 = 0.f;   // ctx col = tid
    const float* memcol = memory + (size_t)b * T_ * EMB_ + tid;

    // ---------- 8 t-tiles: MMA energies + online softmax-context ----------
    for (int it = 0; it < 8; ++it) {
        const int t0g = it * 128;

        __syncthreads();
        {
            __nv_bfloat16* arow = (__nv_bfloat16*)(sm + rowL * (LDAB_ * 2));
            const int base0 = 1 + t0g + rowL;
            #pragma unroll
            for (int q = 0; q < 16; ++q) {
                int j = jq * 16 + q;
                if (j < 62) {
                    float x = (j < 31) ? s_awr[base0 + j] : s_awr[1056 + base0 + (j - 31)];
                    __nv_bfloat16 hi = __float2bfloat16_rn(x);
                    arow[j]      = hi;
                    arow[64 + j] = __float2bfloat16_rn(x - __bfloat162float(hi));
                }
            }
        }
        __syncthreads();

        float acc[8][4];
        #pragma unroll
        for (int n = 0; n < 8; ++n) {
            acc[n][0] = 0.f; acc[n][1] = 0.f; acc[n][2] = 0.f; acc[n][3] = 0.f;
        }
        #pragma unroll
        for (int s = 0; s < 12; ++s) {
            const int ksa = (s < 8) ? s : (s - 8);
            const int ksb = (s < 4) ? s : (s - 4);
            uint32_t af[4];
            ldsm_x4(af, aRowAddr + ksa * 32);
            const uint32_t bS = bRowAddr + ksb * 16 * (LDAB_ * 2);
            #pragma unroll
            for (int n = 0; n < 8; ++n) {
                uint32_t b0, b1;
                ldsm_x2t(b0, b1, bS + n * 16);
                mma_bf16(acc[n], af, b0, b1);
            }
        }

        {
            const int r  = lane >> 2;
            const int cq = (lane & 3) * 2;
            const int tA = t0g + 16 * slab + r;
            const float* pmA = pmem + ((size_t)b * T_ + tA) * ATT_;
            const float* pmB = pmA + 8 * ATT_;
            float eA = 0.f, eB = 0.f;
            #pragma unroll
            for (int n = 0; n < 8; ++n) {
                const int col = 64 * nh + 8 * n + cq;
                float2 v2 = *(const float2*)(s_v + col);
                float2 pa = *(const float2*)(pmA + col);
                float2 pb = *(const float2*)(pmB + col);
                eA = fmaf(tanh_fast(acc[n][0] + pa.x), v2.x, eA);
                eA = fmaf(tanh_fast(acc[n][1] + pa.y), v2.y, eA);
                eB = fmaf(tanh_fast(acc[n][2] + pb.x), v2.x, eB);
                eB = fmaf(tanh_fast(acc[n][3] + pb.y), v2.y, eB);
            }
            eA += __shfl_xor_sync(0xffffffffu, eA, 1);
            eA += __shfl_xor_sync(0xffffffffu, eA, 2);
            eB += __shfl_xor_sync(0xffffffffu, eB, 1);
            eB += __shfl_xor_sync(0xffffffffu, eB, 2);
            if ((lane & 3) == 0) {
                s_e[nh * 1024 + tA]     = eA;
                s_e[nh * 1024 + tA + 8] = eB;
            }
        }
        __syncthreads();

        // combine halves, apply mask, tile max
        if (tid < 128) {
            float e = s_e[t0g + tid] + s_e[1024 + t0g + tid];
            if (mask[(size_t)b * T_ + t0g + tid]) e = NINF;
            s_e[t0g + tid] = e;
            float m = e;
            #pragma unroll
            for (int o = 16; o; o >>= 1) m = fmaxf(m, __shfl_xor_sync(0xffffffffu, m, o));
            if (lane == 0) s_red[wm] = m;
        }
        __syncthreads();

        const float tm = fmaxf(fmaxf(s_red[0], s_red[1]), fmaxf(s_red[2], s_red[3]));
        const float Mp = fmaxf(run_max, tm);
        const float scale = expf(run_max - Mp);
        cacc0 *= scale; cacc1 *= scale; cacc2 *= scale; cacc3 *= scale;
        run_max = Mp;
        if (tid < 128) s_p[tid] = expf(s_e[t0g + tid] - Mp);
        __syncthreads();

        // context accumulate: thread = col, 128 t per tile, 4 chains
        {
            const float* mp = memcol + (size_t)t0g * EMB_;
            #pragma unroll 8
            for (int i = 0; i < 128; i += 4) {
                cacc0 = fmaf(s_p[i + 0], __ldcs(mp + (size_t)(i + 0) * EMB_), cacc0);
                cacc1 = fmaf(s_p[i + 1], __ldcs(mp + (size_t)(i + 1) * EMB_), cacc1);
                cacc2 = fmaf(s_p[i + 2], __ldcs(mp + (size_t)(i + 2) * EMB_), cacc2);
                cacc3 = fmaf(s_p[i + 3], __ldcs(mp + (size_t)(i + 3) * EMB_), cacc3);
            }
        }
    }
    __syncthreads();

    // ---------- finalize: Z from combined energies (run_max is global max) ----------
    {
        float2 ev = ((const float2*)s_e)[tid];
        float2 p;
        p.x = expf(ev.x - run_max); p.y = expf(ev.y - run_max);
        float s = p.x + p.y;
        #pragma unroll
        for (int o = 16; o; o >>= 1) s += __shfl_xor_sync(0xffffffffu, s, o);
        if (lane == 0) s_red[32 + wm] = s;
        __syncthreads();
        if (wm == 0) {
            float ss = (lane < 16) ? s_red[32 + lane] : 0.f;
            #pragma unroll
            for (int o = 8; o; o >>= 1) ss += __shfl_xor_sync(0xffffffffu, ss, o);
            if (lane == 0) s_red[48] = ss;
        }
        __syncthreads();
        const float inv = 1.f / s_red[48];

        p.x *= inv; p.y *= inv;
        ((float2*)(out_w + (size_t)b * T_))[tid] = p;

        float ctx = ((cacc0 + cacc1) + (cacc2 + cacc3)) * inv;
        out[(size_t)b * EMB_ + tid] = ctx;
    }
}

// ============================ launch ============================
extern "C" void kernel_launch(void* const* d_in, const int* in_sizes, int n_in,
                              void* d_out, int out_size) {
    const float* hidden = (const float*)d_in[0];
    const float* memory = (const float*)d_in[1];
    const float* pmem   = (const float*)d_in[2];
    const float* awcat  = (const float*)d_in[3];
    const unsigned char* mask = (const unsigned char*)d_in[4];
    const float* wq     = (const float*)d_in[5];
    const float* wconv  = (const float*)d_in[6];
    const float* wloc   = (const float*)d_in[7];
    const float* vvec   = (const float*)d_in[8];

    float* out = (float*)d_out;

    cudaFuncSetAttribute(fused_kernel,
                         cudaFuncAttributeMaxDynamicSharedMemorySize, ESMEM_);

    fused_kernel<<<B_, 512, ESMEM_>>>(awcat, pmem, vvec, mask,
                                      hidden, wq, wconv, wloc, memory, out);
}

// round 12
// speedup vs baseline: 1.0775x; 1.0775x over previous
#include <cuda_runtime.h>
#include <cuda_bf16.h>
#include <cstdint>

#define B_    128
#define T_    1024
#define RNN_  1024
#define EMB_  512
#define ATT_  128
#define NF_   32
#define KS_   31
#define PAD_  15

// energies GEMM per 128-t tile: D[128,128] = A[t,192] * B[192,a], B dedup to 128 rows
// s0-3: Ahi x Bhi, s4-7: Alo x Bhi, s8-11: Ahi x Blo (A frags of s8-11 == s0-3, cached)
#define LDAB_  136                              // bf16 elems per smem row (272 B)
#define OFF_B_    (128 * LDAB_ * 2)             // 34816
#define OFF_AWR_  (OFF_B_ + 128 * LDAB_ * 2)    // 69632: aw rows 2 x 1056 f
#define OFF_V_    (OFF_AWR_ + 8448)             // 78080
#define OFF_E_    (OFF_V_ + 512)                // 78592: energies 4 x 1024 f (also pq scratch)
#define OFF_RED_  (OFF_E_ + 16384)              // 94976
#define OFF_HID_  (OFF_RED_ + 256)              // 95232: hidden row 1024 f
#define ESMEM_    (OFF_HID_ + 4096)             // 99328

// scratch inside the (not yet built) A region during staging:
#define SCR_WLOC_  0          // 4096 f = 16384 B
#define SCR_WCONV_ 16384      // 1984 f = 7936 B (ends at 24320 < 34816)

// ---------------- helpers ----------------
__device__ __forceinline__ float tanh_fast(float x) {
    float y; asm("tanh.approx.f32 %0, %1;" : "=f"(y) : "f"(x)); return y;
}
__device__ __forceinline__ uint32_t smem_u32(const void* p) {
    uint32_t a;
    asm("{ .reg .u64 t; cvta.to.shared.u64 t, %1; cvt.u32.u64 %0, t; }" : "=r"(a) : "l"(p));
    return a;
}
__device__ __forceinline__ void ldsm_x4(uint32_t* r, uint32_t addr) {
    asm volatile("ldmatrix.sync.aligned.m8n8.x4.shared.b16 {%0,%1,%2,%3}, [%4];"
                 : "=r"(r[0]), "=r"(r[1]), "=r"(r[2]), "=r"(r[3]) : "r"(addr));
}
__device__ __forceinline__ void ldsm_x2t(uint32_t& b0, uint32_t& b1, uint32_t addr) {
    asm volatile("ldmatrix.sync.aligned.m8n8.x2.trans.shared.b16 {%0,%1}, [%2];"
                 : "=r"(b0), "=r"(b1) : "r"(addr));
}
__device__ __forceinline__ void mma_bf16(float* d, const uint32_t* a, uint32_t b0, uint32_t b1) {
    asm volatile("mma.sync.aligned.m16n8k16.row.col.f32.bf16.bf16.f32 "
                 "{%0,%1,%2,%3}, {%4,%5,%6,%7}, {%8,%9}, {%0,%1,%2,%3};"
                 : "+f"(d[0]), "+f"(d[1]), "+f"(d[2]), "+f"(d[3])
                 : "r"(a[0]), "r"(a[1]), "r"(a[2]), "r"(a[3]), "r"(b0), "r"(b1));
}

// ====== K1: fused energies: pq + W2 + MMA(8 t-tiles) + softmax, 1 block/b ======
__global__ __launch_bounds__(512, 1) void energies_softmax_kernel(
    const float* __restrict__ aw,      // [B,2,T]
    const float* __restrict__ pmem,    // [B,T,ATT]
    const float* __restrict__ vvec,    // [ATT]
    const unsigned char* __restrict__ mask,
    const float* __restrict__ hidden,  // [B,RNN]
    const float* __restrict__ wq,      // [RNN,ATT]
    const float* __restrict__ wconv,   // [NF,62]
    const float* __restrict__ wloc,    // [NF,ATT]
    float* __restrict__ out_w)
{
    extern __shared__ __align__(16) char sm[];
    const uint32_t sbase = smem_u32(sm);

    const int b    = blockIdx.x;
    const int tid  = threadIdx.x;
    const int wm   = tid >> 5, lane = tid & 31;
    const int sg   = wm >> 2;          // 0..3: t rows [32*sg, 32*sg+32) (2 slabs)
    const int nq   = wm & 3;           // 0..3: n-tiles [4*nq, 4*nq+4) = cols [32nq, 32nq+32)

    float* s_awr = (float*)(sm + OFF_AWR_);   // [2][1056], s_awr[ch][i] = aw[gt=i-16]
    float* s_v   = (float*)(sm + OFF_V_);
    float* s_e   = (float*)(sm + OFF_E_);     // [4][1024] per-nq partials; pq scratch early
    float* s_red = (float*)(sm + OFF_RED_);
    float* s_hid = (float*)(sm + OFF_HID_);
    __nv_bfloat16* sB = (__nv_bfloat16*)(sm + OFF_B_);

    // ---------- staging ----------
    for (int idx = tid; idx < 2112; idx += 512) {
        int ch = idx / 1056, i = idx - ch * 1056;
        int gt = i - 16;
        s_awr[idx] = (gt >= 0 && gt < T_) ? aw[((size_t)b * 2 + ch) * T_ + gt] : 0.f;
    }
    if (tid < 128) s_v[tid] = vvec[tid];
    s_hid[tid]       = hidden[(size_t)b * RNN_ + tid];
    s_hid[tid + 512] = hidden[(size_t)b * RNN_ + tid + 512];
    {
        float* s_wloc  = (float*)(sm + SCR_WLOC_);
        float* s_wconv = (float*)(sm + SCR_WCONV_);
        #pragma unroll
        for (int i = 0; i < 8; ++i) s_wloc[tid + 512 * i] = wloc[tid + 512 * i];
        for (int m = tid; m < NF_ * 62; m += 512) s_wconv[m] = wconv[m];
    }
    __syncthreads();

    // ---------- phase A: pq partials + W2 -> B rows ----------
    {
        const int kq = tid >> 5, a4 = tid & 31;
        const float4* wq4 = (const float4*)wq + (size_t)(kq * 64) * (ATT_ / 4) + a4;
        const float*  hp  = s_hid + kq * 64;
        float4 acc0 = make_float4(0.f, 0.f, 0.f, 0.f);
        float4 acc1 = make_float4(0.f, 0.f, 0.f, 0.f);
        #pragma unroll 8
        for (int k = 0; k < 64; k += 2) {
            float h0 = hp[k], h1 = hp[k + 1];
            float4 w0 = wq4[(size_t)k * (ATT_ / 4)];
            float4 w1 = wq4[(size_t)(k + 1) * (ATT_ / 4)];
            acc0.x = fmaf(h0, w0.x, acc0.x);
            acc0.y = fmaf(h0, w0.y, acc0.y);
            acc0.z = fmaf(h0, w0.z, acc0.z);
            acc0.w = fmaf(h0, w0.w, acc0.w);
            acc1.x = fmaf(h1, w1.x, acc1.x);
            acc1.y = fmaf(h1, w1.y, acc1.y);
            acc1.z = fmaf(h1, w1.z, acc1.z);
            acc1.w = fmaf(h1, w1.w, acc1.w);
        }
        acc0.x += acc1.x; acc0.y += acc1.y; acc0.z += acc1.z; acc0.w += acc1.w;
        ((float4*)s_e)[kq * 32 + a4] = acc0;

        const float* s_wloc  = (const float*)(sm + SCR_WLOC_);
        const float* s_wconv = (const float*)(sm + SCR_WCONV_);
        for (int m = tid; m < 62 * 128; m += 512) {
            int j = m >> 7, a = m & 127;
            float acc = 0.f;
            #pragma unroll 8
            for (int f = 0; f < NF_; ++f)
                acc = fmaf(s_wconv[f * 62 + j], s_wloc[f * ATT_ + a], acc);
            __nv_bfloat16 hi = __float2bfloat16_rn(acc);
            sB[j * LDAB_ + a]        = hi;
            sB[(64 + j) * LDAB_ + a] = __float2bfloat16_rn(acc - __bfloat162float(hi));
        }
        if (tid < 128) {
            sB[ 63 * LDAB_ + tid] = __float2bfloat16_rn(0.f);
            sB[127 * LDAB_ + tid] = __float2bfloat16_rn(0.f);
        }
    }
    __syncthreads();

    // ---------- phase B: pq reduce -> B rows 62/126; const A cols ----------
    if (tid < 32) {
        float4 r = ((const float4*)s_e)[tid];
        #pragma unroll
        for (int q = 1; q < 16; ++q) {
            float4 v = ((const float4*)s_e)[q * 32 + tid];
            r.x += v.x; r.y += v.y; r.z += v.z; r.w += v.w;
        }
        float vals[4] = {r.x, r.y, r.z, r.w};
        #pragma unroll
        for (int c = 0; c < 4; ++c) {
            int col = 4 * tid + c;
            __nv_bfloat16 hi = __float2bfloat16_rn(vals[c]);
            sB[ 62 * LDAB_ + col] = hi;
            sB[126 * LDAB_ + col] = __float2bfloat16_rn(vals[c] - __bfloat162float(hi));
        }
    }
    if (tid < 128) {
        __nv_bfloat16* arow = (__nv_bfloat16*)(sm + tid * (LDAB_ * 2));
        arow[62]  = __float2bfloat16_rn(1.f);
        arow[63]  = __float2bfloat16_rn(0.f);
        arow[126] = __float2bfloat16_rn(0.f);
        arow[127] = __float2bfloat16_rn(0.f);
    }

    const uint32_t aAddr0 = sbase + (32 * sg + (lane & 15)) * (LDAB_ * 2) + (lane >> 4) * 16;
    const uint32_t aAddr1 = aAddr0 + 16 * (LDAB_ * 2);
    const uint32_t bAddrQ = sbase + OFF_B_ + (lane & 15) * (LDAB_ * 2) + nq * 64;
    const int rowL = tid >> 2;            // A row this thread builds
    const int jq   = tid & 3;             // 16-col group within the row

    // ---------- 8 t-tiles ----------
    for (int it = 0; it < 8; ++it) {
        const int t0g = it * 128;

        __syncthreads();
        {
            __nv_bfloat16* arow = (__nv_bfloat16*)(sm + rowL * (LDAB_ * 2));
            const int base0 = 1 + t0g + rowL;
            #pragma unroll
            for (int q = 0; q < 16; ++q) {
                int j = jq * 16 + q;
                if (j < 62) {
                    float x = (j < 31) ? s_awr[base0 + j] : s_awr[1056 + base0 + (j - 31)];
                    __nv_bfloat16 hi = __float2bfloat16_rn(x);
                    arow[j]      = hi;
                    arow[64 + j] = __float2bfloat16_rn(x - __bfloat162float(hi));
                }
            }
        }
        __syncthreads();

        // MMA: warp covers 32 t-rows (2 slabs) x 32 cols (4 n-tiles), A hi-frags cached
        float acc0[4][4], acc1[4][4];
        uint32_t afc0[4][4], afc1[4][4];
        #pragma unroll
        for (int n = 0; n < 4; ++n) {
            acc0[n][0] = 0.f; acc0[n][1] = 0.f; acc0[n][2] = 0.f; acc0[n][3] = 0.f;
            acc1[n][0] = 0.f; acc1[n][1] = 0.f; acc1[n][2] = 0.f; acc1[n][3] = 0.f;
        }
        #pragma unroll
        for (int s = 0; s < 12; ++s) {
            uint32_t afr0[4], afr1[4];
            const uint32_t* a0;
            const uint32_t* a1;
            if (s < 4) {
                ldsm_x4(afc0[s], aAddr0 + s * 32);
                ldsm_x4(afc1[s], aAddr1 + s * 32);
                a0 = afc0[s]; a1 = afc1[s];
            } else if (s < 8) {
                ldsm_x4(afr0, aAddr0 + s * 32);
                ldsm_x4(afr1, aAddr1 + s * 32);
                a0 = afr0; a1 = afr1;
            } else {
                a0 = afc0[s - 8]; a1 = afc1[s - 8];
            }
            const int ksb = (s < 4) ? s : (s - 4);
            const uint32_t bS = bAddrQ + ksb * 16 * (LDAB_ * 2);
            #pragma unroll
            for (int n = 0; n < 4; ++n) {
                uint32_t b0, b1;
                ldsm_x2t(b0, b1, bS + n * 16);
                mma_bf16(acc0[n], a0, b0, b1);
                mma_bf16(acc1[n], a1, b0, b1);
            }
        }

        // epilogue: rows of both slabs, cols [32nq, 32nq+32)
        {
            const int r  = lane >> 2;
            const int cq = (lane & 3) * 2;
            #pragma unroll
            for (int h = 0; h < 2; ++h) {
                const int tA = t0g + 32 * sg + 16 * h + r;
                const float* pmA = pmem + ((size_t)b * T_ + tA) * ATT_;
                const float* pmB = pmA + 8 * ATT_;
                float (*ac)[4] = h ? acc1 : acc0;
                float eA = 0.f, eB = 0.f;
                #pragma unroll
                for (int n = 0; n < 4; ++n) {
                    const int col = 32 * nq + 8 * n + cq;
                    float2 v2 = *(const float2*)(s_v + col);
                    float2 pa = *(const float2*)(pmA + col);
                    float2 pb = *(const float2*)(pmB + col);
                    eA = fmaf(tanh_fast(ac[n][0] + pa.x), v2.x, eA);
                    eA = fmaf(tanh_fast(ac[n][1] + pa.y), v2.y, eA);
                    eB = fmaf(tanh_fast(ac[n][2] + pb.x), v2.x, eB);
                    eB = fmaf(tanh_fast(ac[n][3] + pb.y), v2.y, eB);
                }
                eA += __shfl_xor_sync(0xffffffffu, eA, 1);
                eA += __shfl_xor_sync(0xffffffffu, eA, 2);
                eB += __shfl_xor_sync(0xffffffffu, eB, 1);
                eB += __shfl_xor_sync(0xffffffffu, eB, 2);
                if ((lane & 3) == 0) {
                    s_e[nq * 1024 + tA]     = eA;
                    s_e[nq * 1024 + tA + 8] = eB;
                }
            }
        }
    }
    __syncthreads();

    // ---------- fused softmax over 1024 energies (combine 4 nq planes) ----------
    {
        float2 e0 = ((const float2*)s_e)[tid];
        float2 e1 = ((const float2*)(s_e + 1024))[tid];
        float2 e2 = ((const float2*)(s_e + 2048))[tid];
        float2 e3 = ((const float2*)(s_e + 3072))[tid];
        float2 ev;
        ev.x = (e0.x + e1.x) + (e2.x + e3.x);
        ev.y = (e0.y + e1.y) + (e2.y + e3.y);
        const uchar2 mk = ((const uchar2*)(mask + (size_t)b * T_))[tid];
        const float NINF = -__int_as_float(0x7f800000);
        if (mk.x) ev.x = NINF;
        if (mk.y) ev.y = NINF;

        float m = fmaxf(ev.x, ev.y);
        #pragma unroll
        for (int o = 16; o; o >>= 1) m = fmaxf(m, __shfl_xor_sync(0xffffffffu, m, o));
        if (lane == 0) s_red[wm] = m;
        __syncthreads();
        if (wm == 0) {
            float mm = (lane < 16) ? s_red[lane] : NINF;
            #pragma unroll
            for (int o = 8; o; o >>= 1) mm = fmaxf(mm, __shfl_xor_sync(0xffffffffu, mm, o));
            if (lane == 0) s_red[16] = mm;
        }
        __syncthreads();
        m = s_red[16];

        float2 p;
        p.x = expf(ev.x - m); p.y = expf(ev.y - m);
        float s = p.x + p.y;
        #pragma unroll
        for (int o = 16; o; o >>= 1) s += __shfl_xor_sync(0xffffffffu, s, o);
        if (lane == 0) s_red[32 + wm] = s;
        __syncthreads();
        if (wm == 0) {
            float ss = (lane < 16) ? s_red[32 + lane] : 0.f;
            #pragma unroll
            for (int o = 8; o; o >>= 1) ss += __shfl_xor_sync(0xffffffffu, ss, o);
            if (lane == 0) s_red[48] = ss;
        }
        __syncthreads();
        const float inv = 1.f / s_red[48];

        p.x *= inv; p.y *= inv;
        ((float2*)(out_w + (size_t)b * T_))[tid] = p;
    }
}

// ============ K2: context, single pass: grid (4, B_), 512 thr ============
__global__ __launch_bounds__(512) void context_kernel(
    const float* __restrict__ memory,   // [B,T,EMB]
    const float* __restrict__ out_w,    // weights [B,T]
    float* __restrict__ out)            // context [B,EMB]
{
    const int ec = blockIdx.x, b = blockIdx.y;
    const int tid = threadIdx.x;
    const int g = tid >> 5, l = tid & 31;   // g: t-phase (0..15), l: float4 lane

    __shared__ float s_w[T_];
    __shared__ float4 s_acc[512];

    s_w[tid]       = out_w[(size_t)b * T_ + tid];
    s_w[tid + 512] = out_w[(size_t)b * T_ + tid + 512];
    __syncthreads();

    const float4* mem4 = (const float4*)memory + ((size_t)b * T_) * (EMB_ / 4) + ec * 32 + l;
    float4 acc = make_float4(0.f, 0.f, 0.f, 0.f);
    #pragma unroll 4
    for (int t = g; t < T_; t += 16) {
        float wt = s_w[t];
        float4 mv = __ldcs(mem4 + (size_t)t * (EMB_ / 4));
        acc.x = fmaf(wt, mv.x, acc.x);
        acc.y = fmaf(wt, mv.y, acc.y);
        acc.z = fmaf(wt, mv.z, acc.z);
        acc.w = fmaf(wt, mv.w, acc.w);
    }
    s_acc[tid] = acc;
    __syncthreads();
    if (g < 8) {
        float4 o = s_acc[tid + 256];
        acc.x += o.x; acc.y += o.y; acc.z += o.z; acc.w += o.w;
        s_acc[tid] = acc;
    }
    __syncthreads();
    if (g < 4) {
        float4 o = s_acc[tid + 128];
        acc.x += o.x; acc.y += o.y; acc.z += o.z; acc.w += o.w;
        s_acc[tid] = acc;
    }
    __syncthreads();
    if (g < 2) {
        float4 o = s_acc[tid + 64];
        acc.x += o.x; acc.y += o.y; acc.z += o.z; acc.w += o.w;
        s_acc[tid] = acc;
    }
    __syncthreads();
    if (g == 0) {
        float4 o = s_acc[tid + 32];
        acc.x += o.x; acc.y += o.y; acc.z += o.z; acc.w += o.w;
        ((float4*)out)[(size_t)b * (EMB_ / 4) + ec * 32 + l] = acc;
    }
}

// ============================ launch ============================
extern "C" void kernel_launch(void* const* d_in, const int* in_sizes, int n_in,
                              void* d_out, int out_size) {
    const float* hidden = (const float*)d_in[0];
    const float* memory = (const float*)d_in[1];
    const float* pmem   = (const float*)d_in[2];
    const float* awcat  = (const float*)d_in[3];
    const unsigned char* mask = (const unsigned char*)d_in[4];
    const float* wq     = (const float*)d_in[5];
    const float* wconv  = (const float*)d_in[6];
    const float* wloc   = (const float*)d_in[7];
    const float* vvec   = (const float*)d_in[8];

    float* out   = (float*)d_out;
    float* out_w = out + (size_t)B_ * EMB_;

    cudaFuncSetAttribute(energies_softmax_kernel,
                         cudaFuncAttributeMaxDynamicSharedMemorySize, ESMEM_);

    energies_softmax_kernel<<<B_, 512, ESMEM_>>>(awcat, pmem, vvec, mask,
                                                 hidden, wq, wconv, wloc, out_w);
    context_kernel<<<dim3(4, B_), 512>>>(memory, out_w, out);
}